// round 7
// baseline (speedup 1.0000x reference)
#include <cuda_runtime.h>
#include <cuda_bf16.h>
#include <cstdint>

// Problem constants
#define BB 32
#define CC 256
#define NNV 1024
#define KK 3136
#define MM (BB * CC)        // 8192
#define K2 (2 * KK)         // 6272 (hi | lo)

// GEMM tiling (sm80-style HMMA, 3-stage cp.async multistage, static smem 48KB)
#define BM 128
#define BN 128
#define BK 32
#define KSEG 98             // 3136/32 chunks per segment
#define NCHUNK (3 * KSEG)   // 294: segments (Ah,Bh), (Al,Bh), (Ah,Bl)
#define NSTAGE 3
#define STAGE_ELEMS (2 * BM * BK)              // A 4096 + B 4096 bf16

// Scratch (device globals: no allocation allowed)
__device__ __nv_bfloat16 g_A2[(size_t)MM * K2];    // x split  [hi | lo]
__device__ __nv_bfloat16 g_B2[(size_t)NNV * K2];   // Ws split [hi | lo]
__device__ float g_y[(size_t)MM * NNV];
__device__ float g_wdt[(size_t)CC * NNV];

__device__ __forceinline__ uint32_t smem_u32(const void* p) {
    uint32_t a;
    asm("{ .reg .u64 t; cvta.to.shared.u64 t, %1; cvt.u32.u64 %0, t; }" : "=r"(a) : "l"(p));
    return a;
}
#define CP16(dst, src)  asm volatile("cp.async.cg.shared.global [%0], [%1], 16;" :: "r"(dst), "l"(src) : "memory")
#define CP_COMMIT()     asm volatile("cp.async.commit_group;" ::: "memory")
#define CP_WAIT1()      asm volatile("cp.async.wait_group 1;" ::: "memory")
#define CP_WAIT0()      asm volatile("cp.async.wait_group 0;" ::: "memory")

#define LDSM_X4(r0, r1, r2, r3, a) \
    asm volatile("ldmatrix.sync.aligned.m8n8.x4.shared.b16 {%0,%1,%2,%3}, [%4];" \
        : "=r"(r0), "=r"(r1), "=r"(r2), "=r"(r3) : "r"(a))

#define MMA16816(d, a, b) \
    asm volatile("mma.sync.aligned.m16n8k16.row.col.f32.bf16.bf16.f32 " \
        "{%0,%1,%2,%3}, {%4,%5,%6,%7}, {%8,%9}, {%0,%1,%2,%3};" \
        : "+f"((d)[0]), "+f"((d)[1]), "+f"((d)[2]), "+f"((d)[3]) \
        : "r"((a)[0]), "r"((a)[1]), "r"((a)[2]), "r"((a)[3]), "r"((b)[0]), "r"((b)[1]))

// Row = 32 bf16 = 64B = 4x16B units; swizzle u^((row>>1)&3) -> ldmatrix conflict-free
__device__ __forceinline__ uint32_t swz(int row, int u) {
    return (uint32_t)(row * 64 + ((u ^ ((row >> 1) & 3)) << 4));
}

// ---------------- split-to-bf16 conversion ----------------
__device__ __forceinline__ void split4(float4 v, uint2& hp, uint2& lp) {
    float a[4] = {v.x, v.y, v.z, v.w};
    uint32_t h[4], l[4];
#pragma unroll
    for (int i = 0; i < 4; i++) {
        __nv_bfloat16 hb = __float2bfloat16(a[i]);
        float res = a[i] - __bfloat162float(hb);
        __nv_bfloat16 lb = __float2bfloat16(res);
        h[i] = __bfloat16_as_ushort(hb);
        l[i] = __bfloat16_as_ushort(lb);
    }
    hp.x = h[0] | (h[1] << 16); hp.y = h[2] | (h[3] << 16);
    lp.x = l[0] | (l[1] << 16); lp.y = l[2] | (l[3] << 16);
}

__global__ void __launch_bounds__(256) split_x(const float* __restrict__ src) {
    size_t i = (size_t)blockIdx.x * 256 + threadIdx.x;
    size_t r = i / (KK / 4); int k4 = (int)(i % (KK / 4));
    float4 v = ((const float4*)src)[i];
    uint2 hp, lp; split4(v, hp, lp);
    __nv_bfloat16* row = g_A2 + r * K2;
    *(uint2*)(row + (size_t)k4 * 4)      = hp;
    *(uint2*)(row + KK + (size_t)k4 * 4) = lp;
}

__global__ void __launch_bounds__(256) split_w(const float* __restrict__ src) {
    size_t i = (size_t)blockIdx.x * 256 + threadIdx.x;
    size_t r = i / (KK / 4); int k4 = (int)(i % (KK / 4));
    float4 v = ((const float4*)src)[i];
    uint2 hp, lp; split4(v, hp, lp);
    __nv_bfloat16* row = g_B2 + r * K2;
    *(uint2*)(row + (size_t)k4 * 4)      = hp;
    *(uint2*)(row + KK + (size_t)k4 * 4) = lp;
}

// ---------------- HMMA GEMM: y = A2 x B2^T, 3-stage pipeline (static smem) ----------------
__global__ void __launch_bounds__(256, 2) gemm_hmma() {
    __shared__ __align__(128) __nv_bfloat16 stg[NSTAGE][STAGE_ELEMS];   // 49152 B

    const int tid = threadIdx.x;
    const int wid = tid >> 5, lid = tid & 31;
    const int wm = (wid & 1) * 64;        // warp m base (2 warps in m)
    const int wn = (wid >> 1) * 32;       // warp n base (4 warps in n)
    const int m0 = blockIdx.y * BM;
    const int n0 = blockIdx.x * BN;

    const uint32_t s0 = smem_u32(&stg[0][0]);
    // stage s: A at s*16K, B at s*16K + 8K

    float acc[4][4][4];
#pragma unroll
    for (int i = 0; i < 4; i++)
#pragma unroll
        for (int j = 0; j < 4; j++)
#pragma unroll
            for (int q = 0; q < 4; q++) acc[i][j][q] = 0.f;

    // loader: chunk c (k32), stage s. 512 16B-units for A, 512 for B.
    auto load_chunk = [&](int c, int s) {
        const int seg = c / KSEG, kc = c % KSEG;
        const int acol = ((seg == 1) ? KK : 0) + kc * BK;
        const int bcol = ((seg == 2) ? KK : 0) + kc * BK;
        const __nv_bfloat16* ap = g_A2 + (size_t)m0 * K2 + acol;
        const __nv_bfloat16* bp = g_B2 + (size_t)n0 * K2 + bcol;
        const uint32_t sa = s0 + s * (STAGE_ELEMS * 2);
        const uint32_t sb = sa + BM * BK * 2;
#pragma unroll
        for (int i = 0; i < 2; i++) {
            int q = tid + i * 256;
            int row = q >> 2, u = q & 3;
            CP16(sa + swz(row, u), ap + (size_t)row * K2 + u * 8);
            CP16(sb + swz(row, u), bp + (size_t)row * K2 + u * 8);
        }
        CP_COMMIT();
    };

    load_chunk(0, 0);
    load_chunk(1, 1);

    int s = 0;                 // stage of chunk c
#pragma unroll 1
    for (int c = 0; c < NCHUNK; c++) {
        // pending groups entering iter: {c, c+1 (if exists)}; ensure c done
        if (c < NCHUNK - 1) { CP_WAIT1(); }
        else                { CP_WAIT0(); }
        __syncthreads();
        // stage of chunk c+2 is (c+2)%3 == (c-1)%3: consumed before barrier above
        int sn = (s + 2 >= NSTAGE) ? s + 2 - NSTAGE : s + 2;
        if (c + 2 < NCHUNK) load_chunk(c + 2, sn);

        const uint32_t sa = s0 + s * (STAGE_ELEMS * 2);
        const uint32_t sb = sa + BM * BK * 2;
#pragma unroll
        for (int st = 0; st < 2; st++) {           // two k16 steps
            uint32_t af[4][4];
#pragma unroll
            for (int mf = 0; mf < 4; mf++) {
                int row = wm + mf * 16 + (lid & 15);
                int u = st * 2 + (lid >> 4);
                LDSM_X4(af[mf][0], af[mf][1], af[mf][2], af[mf][3], sa + swz(row, u));
            }
            uint32_t bf[4][2];
#pragma unroll
            for (int p = 0; p < 2; p++) {          // n8-tile pairs
                int t = lid >> 3;
                int row = wn + (p * 2 + (t >> 1)) * 8 + (lid & 7);
                int u = st * 2 + (t & 1);
                LDSM_X4(bf[p * 2][0], bf[p * 2][1], bf[p * 2 + 1][0], bf[p * 2 + 1][1],
                        sb + swz(row, u));
            }
#pragma unroll
            for (int mf = 0; mf < 4; mf++)
#pragma unroll
                for (int nf = 0; nf < 4; nf++)
                    MMA16816(acc[mf][nf], af[mf], bf[nf]);
        }
        s = (s + 1 >= NSTAGE) ? 0 : s + 1;
    }

    // epilogue: c frag (row lid/4 [+8], col (lid%4)*2)
    const int mrow = m0 + wm + (lid >> 2);
    const int ncol = n0 + wn + (lid & 3) * 2;
#pragma unroll
    for (int mf = 0; mf < 4; mf++)
#pragma unroll
        for (int nf = 0; nf < 4; nf++) {
            float* p0 = g_y + (size_t)(mrow + mf * 16) * NNV + ncol + nf * 8;
            float* p1 = p0 + 8 * NNV;
            p0[0] = acc[mf][nf][0]; p0[1] = acc[mf][nf][1];
            p1[0] = acc[mf][nf][2]; p1[1] = acc[mf][nf][3];
        }
}

// ---------------- second contraction ----------------
__global__ void __launch_bounds__(256) transpose_wd(const float* __restrict__ Wd) {
    int idx = blockIdx.x * 256 + threadIdx.x;
    int c = idx >> 10, n = idx & 1023;
    g_wdt[idx] = Wd[(size_t)n * CC + c];
}

__global__ void __launch_bounds__(256) reduce_k(const float* __restrict__ Wb, float* __restrict__ out) {
    int idx = blockIdx.x * 256 + threadIdx.x;
    int b = idx >> 10, n = idx & 1023;
    const float* y = g_y + ((size_t)b * CC) * NNV + n;
    float s = 0.f;
#pragma unroll 8
    for (int c = 0; c < CC; c++)
        s = fmaf(y[(size_t)c * NNV], g_wdt[(size_t)c * NNV + n], s);
    out[idx] = s + Wb[n];
}

extern "C" void kernel_launch(void* const* d_in, const int* in_sizes, int n_in,
                              void* d_out, int out_size) {
    const float* x  = (const float*)d_in[0];   // (B, C, H, W)
    const float* Ws = (const float*)d_in[1];   // (N, H, W)
    const float* Wd = (const float*)d_in[2];   // (N, C, 1, 1)
    const float* Wb = (const float*)d_in[3];   // (1, N)
    float* out = (float*)d_out;                // (B, N)

    split_x<<<(MM * (KK / 4)) / 256, 256>>>(x);
    split_w<<<(NNV * (KK / 4)) / 256, 256>>>(Ws);
    transpose_wd<<<(CC * NNV) / 256, 256>>>(Wd);
    dim3 grid(NNV / BN, MM / BM);              // (8, 64)
    gemm_hmma<<<grid, 256>>>();
    reduce_k<<<(BB * NNV) / 256, 256>>>(Wb, out);
}

// round 9
// speedup vs baseline: 1.0001x; 1.0001x over previous
#include <cuda_runtime.h>
#include <cuda_bf16.h>
#include <cstdint>

// Problem constants
#define BB 32
#define CC 256
#define NNV 1024
#define KK 3136
#define MM (BB * CC)        // 8192
#define K2 (2 * KK)         // 6272 (hi | lo)

// GEMM tiling: BM=64, BN=128, warp tile 32x32, 8 warps (2m x 4n), 3 CTAs/SM
#define BM 64
#define BN 128
#define BK 32
#define KSEG 98             // 3136/32 chunks per segment
#define NCHUNK (3 * KSEG)   // 294: segments (Ah,Bh), (Al,Bh), (Ah,Bl)
#define NSTAGE 3
#define STAGE_ELEMS ((BM + BN) * BK)           // 6144 bf16 = 12KB

// Scratch (device globals: no allocation allowed)
__device__ __nv_bfloat16 g_A2[(size_t)MM * K2];    // x split  [hi | lo]
__device__ __nv_bfloat16 g_B2[(size_t)NNV * K2];   // Ws split [hi | lo]
__device__ float g_y[(size_t)MM * NNV];
__device__ float g_wdt[(size_t)CC * NNV];

__device__ __forceinline__ uint32_t smem_u32(const void* p) {
    uint32_t a;
    asm("{ .reg .u64 t; cvta.to.shared.u64 t, %1; cvt.u32.u64 %0, t; }" : "=r"(a) : "l"(p));
    return a;
}
#define CP16(dst, src)  asm volatile("cp.async.cg.shared.global [%0], [%1], 16;" :: "r"(dst), "l"(src) : "memory")
#define CP_COMMIT()     asm volatile("cp.async.commit_group;" ::: "memory")
#define CP_WAIT1()      asm volatile("cp.async.wait_group 1;" ::: "memory")
#define CP_WAIT0()      asm volatile("cp.async.wait_group 0;" ::: "memory")

#define LDSM_X4(r0, r1, r2, r3, a) \
    asm volatile("ldmatrix.sync.aligned.m8n8.x4.shared.b16 {%0,%1,%2,%3}, [%4];" \
        : "=r"(r0), "=r"(r1), "=r"(r2), "=r"(r3) : "r"(a))

#define MMA16816(d, a, b) \
    asm volatile("mma.sync.aligned.m16n8k16.row.col.f32.bf16.bf16.f32 " \
        "{%0,%1,%2,%3}, {%4,%5,%6,%7}, {%8,%9}, {%0,%1,%2,%3};" \
        : "+f"((d)[0]), "+f"((d)[1]), "+f"((d)[2]), "+f"((d)[3]) \
        : "r"((a)[0]), "r"((a)[1]), "r"((a)[2]), "r"((a)[3]), "r"((b)[0]), "r"((b)[1]))

// Row = 32 bf16 = 64B = 4x16B units; swizzle u^((row>>1)&3) -> ldmatrix conflict-free
__device__ __forceinline__ uint32_t swz(int row, int u) {
    return (uint32_t)(row * 64 + ((u ^ ((row >> 1) & 3)) << 4));
}

// ---------------- split-to-bf16 conversion ----------------
__device__ __forceinline__ void split4(float4 v, uint2& hp, uint2& lp) {
    float a[4] = {v.x, v.y, v.z, v.w};
    uint32_t h[4], l[4];
#pragma unroll
    for (int i = 0; i < 4; i++) {
        __nv_bfloat16 hb = __float2bfloat16(a[i]);
        float res = a[i] - __bfloat162float(hb);
        __nv_bfloat16 lb = __float2bfloat16(res);
        h[i] = __bfloat16_as_ushort(hb);
        l[i] = __bfloat16_as_ushort(lb);
    }
    hp.x = h[0] | (h[1] << 16); hp.y = h[2] | (h[3] << 16);
    lp.x = l[0] | (l[1] << 16); lp.y = l[2] | (l[3] << 16);
}

__global__ void __launch_bounds__(256) split_x(const float* __restrict__ src) {
    size_t i = (size_t)blockIdx.x * 256 + threadIdx.x;
    size_t r = i / (KK / 4); int k4 = (int)(i % (KK / 4));
    float4 v = ((const float4*)src)[i];
    uint2 hp, lp; split4(v, hp, lp);
    __nv_bfloat16* row = g_A2 + r * K2;
    *(uint2*)(row + (size_t)k4 * 4)      = hp;
    *(uint2*)(row + KK + (size_t)k4 * 4) = lp;
}

__global__ void __launch_bounds__(256) split_w(const float* __restrict__ src) {
    size_t i = (size_t)blockIdx.x * 256 + threadIdx.x;
    size_t r = i / (KK / 4); int k4 = (int)(i % (KK / 4));
    float4 v = ((const float4*)src)[i];
    uint2 hp, lp; split4(v, hp, lp);
    __nv_bfloat16* row = g_B2 + r * K2;
    *(uint2*)(row + (size_t)k4 * 4)      = hp;
    *(uint2*)(row + KK + (size_t)k4 * 4) = lp;
}

// ---------------- HMMA GEMM: y = A2 x B2^T, 3-stage pipeline, 3 CTAs/SM ----------------
__global__ void __launch_bounds__(256, 3) gemm_hmma() {
    __shared__ __align__(128) __nv_bfloat16 stg[NSTAGE][STAGE_ELEMS];   // 36864 B

    const int tid = threadIdx.x;
    const int wid = tid >> 5, lid = tid & 31;
    const int wm = (wid & 1) * 32;        // warp m base (2 warps in m)
    const int wn = (wid >> 1) * 32;       // warp n base (4 warps in n)
    const int m0 = blockIdx.y * BM;
    const int n0 = blockIdx.x * BN;

    const uint32_t s0 = smem_u32(&stg[0][0]);
    // stage s: A (64 rows) at s*12K, B (128 rows) at s*12K + 4K

    float acc[2][4][4];
#pragma unroll
    for (int i = 0; i < 2; i++)
#pragma unroll
        for (int j = 0; j < 4; j++)
#pragma unroll
            for (int q = 0; q < 4; q++) acc[i][j][q] = 0.f;

    // loader: chunk c (k32), stage s. A 256 + B 512 16B-units, 3 per thread.
    auto load_chunk = [&](int c, int s) {
        const int seg = c / KSEG, kc = c % KSEG;
        const int acol = ((seg == 1) ? KK : 0) + kc * BK;
        const int bcol = ((seg == 2) ? KK : 0) + kc * BK;
        const __nv_bfloat16* ap = g_A2 + (size_t)m0 * K2 + acol;
        const __nv_bfloat16* bp = g_B2 + (size_t)n0 * K2 + bcol;
        const uint32_t sa = s0 + s * (STAGE_ELEMS * 2);
        const uint32_t sb = sa + BM * BK * 2;
#pragma unroll
        for (int i = 0; i < 3; i++) {
            int q = i * 256 + tid;
            if (q < 256) {
                int row = q >> 2, u = q & 3;
                CP16(sa + swz(row, u), ap + (size_t)row * K2 + u * 8);
            } else {
                int r = q - 256;
                int row = r >> 2, u = r & 3;
                CP16(sb + swz(row, u), bp + (size_t)row * K2 + u * 8);
            }
        }
        CP_COMMIT();
    };

    load_chunk(0, 0);
    load_chunk(1, 1);

    int s = 0;                 // stage of chunk c
#pragma unroll 1
    for (int c = 0; c < NCHUNK; c++) {
        // pending groups entering iter: {c, c+1 (if exists)}; ensure c done
        if (c < NCHUNK - 1) { CP_WAIT1(); }
        else                { CP_WAIT0(); }
        __syncthreads();
        // stage of chunk c+2 is (c+2)%3 == (c-1)%3: consumed before barrier above
        int sn = (s + 2 >= NSTAGE) ? s + 2 - NSTAGE : s + 2;
        if (c + 2 < NCHUNK) load_chunk(c + 2, sn);

        const uint32_t sa = s0 + s * (STAGE_ELEMS * 2);
        const uint32_t sb = sa + BM * BK * 2;
#pragma unroll
        for (int st = 0; st < 2; st++) {           // two k16 steps
            uint32_t af[2][4];
#pragma unroll
            for (int mf = 0; mf < 2; mf++) {
                int row = wm + mf * 16 + (lid & 15);
                int u = st * 2 + (lid >> 4);
                LDSM_X4(af[mf][0], af[mf][1], af[mf][2], af[mf][3], sa + swz(row, u));
            }
            uint32_t bf[4][2];
#pragma unroll
            for (int p = 0; p < 2; p++) {          // n8-tile pairs
                int t = lid >> 3;
                int row = wn + (p * 2 + (t >> 1)) * 8 + (lid & 7);
                int u = st * 2 + (t & 1);
                LDSM_X4(bf[p * 2][0], bf[p * 2][1], bf[p * 2 + 1][0], bf[p * 2 + 1][1],
                        sb + swz(row, u));
            }
#pragma unroll
            for (int mf = 0; mf < 2; mf++)
#pragma unroll
                for (int nf = 0; nf < 4; nf++)
                    MMA16816(acc[mf][nf], af[mf], bf[nf]);
        }
        s = (s + 1 >= NSTAGE) ? 0 : s + 1;
    }

    // epilogue: c frag (row lid/4 [+8], col (lid%4)*2)
    const int mrow = m0 + wm + (lid >> 2);
    const int ncol = n0 + wn + (lid & 3) * 2;
#pragma unroll
    for (int mf = 0; mf < 2; mf++)
#pragma unroll
        for (int nf = 0; nf < 4; nf++) {
            float* p0 = g_y + (size_t)(mrow + mf * 16) * NNV + ncol + nf * 8;
            float* p1 = p0 + 8 * NNV;
            p0[0] = acc[mf][nf][0]; p0[1] = acc[mf][nf][1];
            p1[0] = acc[mf][nf][2]; p1[1] = acc[mf][nf][3];
        }
}

// ---------------- second contraction ----------------
__global__ void __launch_bounds__(256) transpose_wd(const float* __restrict__ Wd) {
    int idx = blockIdx.x * 256 + threadIdx.x;
    int c = idx >> 10, n = idx & 1023;
    g_wdt[idx] = Wd[(size_t)n * CC + c];
}

__global__ void __launch_bounds__(256) reduce_k(const float* __restrict__ Wb, float* __restrict__ out) {
    int idx = blockIdx.x * 256 + threadIdx.x;
    int b = idx >> 10, n = idx & 1023;
    const float* y = g_y + ((size_t)b * CC) * NNV + n;
    float s = 0.f;
#pragma unroll 8
    for (int c = 0; c < CC; c++)
        s = fmaf(y[(size_t)c * NNV], g_wdt[(size_t)c * NNV + n], s);
    out[idx] = s + Wb[n];
}

extern "C" void kernel_launch(void* const* d_in, const int* in_sizes, int n_in,
                              void* d_out, int out_size) {
    const float* x  = (const float*)d_in[0];   // (B, C, H, W)
    const float* Ws = (const float*)d_in[1];   // (N, H, W)
    const float* Wd = (const float*)d_in[2];   // (N, C, 1, 1)
    const float* Wb = (const float*)d_in[3];   // (1, N)
    float* out = (float*)d_out;                // (B, N)

    split_x<<<(MM * (KK / 4)) / 256, 256>>>(x);
    split_w<<<(NNV * (KK / 4)) / 256, 256>>>(Ws);
    transpose_wd<<<(CC * NNV) / 256, 256>>>(Wd);
    dim3 grid(NNV / BN, MM / BM);              // (8, 128)
    gemm_hmma<<<grid, 256>>>();
    reduce_k<<<(BB * NNV) / 256, 256>>>(Wb, out);
}